// round 1
// baseline (speedup 1.0000x reference)
#include <cuda_runtime.h>
#include <cstdint>

// Problem constants
#define SEQ   2048
#define BATCH 2
#define EMB   1024
#define NH    16
#define DH    64
#define MROWS (SEQ * BATCH)  // 4096

static const size_t OUT_ELEMS  = (size_t)MROWS * EMB;          // 4,194,304
static const size_t ATTN_ELEMS = (size_t)BATCH * NH * SEQ * SEQ; // 134,217,728

// Scratch (allocation-free rule: __device__ globals)
__device__ float g_Q[BATCH * NH * SEQ * DH];   // (b,h,n,dh), scale folded in
__device__ float g_K[BATCH * NH * SEQ * DH];
__device__ float g_V[BATCH * NH * SEQ * DH];
__device__ float g_O[MROWS * EMB];             // (n,b,e) layout
__device__ float g_S[BATCH * NH * SEQ * SEQ];  // attn fallback scratch
__device__ float g_OUT_FB[MROWS * EMB];        // out fallback scratch

// ---------------------------------------------------------------------------
// SGEMM 128x128x16, C = A * B^T.  A: [M,1024] row-major, B: [N,1024] row-major.
// DEST = 0/1/2 : write to g_Q/g_K/g_V in (b,h,n,dh) layout, multiplied by scale
// DEST = 3    : write row-major [M,EMB] + bias to out_ext (or g_OUT_FB)
// For DEST==3 the A operand is g_O (referenced directly).
// ---------------------------------------------------------------------------
template <int DEST>
__global__ __launch_bounds__(256) void sgemm128(const float* __restrict__ A_ext,
                                                const float* __restrict__ B,
                                                const float* __restrict__ bias,
                                                float scale,
                                                float* __restrict__ out_ext,
                                                int out_is_fb)
{
    __shared__ float As[16][128];
    __shared__ float Bs[16][128];
    const float* A = (DEST == 3) ? (const float*)g_O : A_ext;

    const int K  = EMB;
    const int bm = blockIdx.y * 128;
    const int bn = blockIdx.x * 128;
    const int tid = threadIdx.x;
    const int tx = tid & 15;
    const int ty = tid >> 4;
    const int lrow = tid >> 2;         // 0..63
    const int lcol = (tid & 3) << 2;   // 0,4,8,12

    float acc[8][8];
#pragma unroll
    for (int i = 0; i < 8; ++i)
#pragma unroll
        for (int j = 0; j < 8; ++j) acc[i][j] = 0.0f;

    for (int kt = 0; kt < K; kt += 16) {
#pragma unroll
        for (int p = 0; p < 2; ++p) {
            int r = (p << 6) + lrow;
            float4 va = *(const float4*)(A + (size_t)(bm + r) * K + kt + lcol);
            As[lcol + 0][r] = va.x; As[lcol + 1][r] = va.y;
            As[lcol + 2][r] = va.z; As[lcol + 3][r] = va.w;
            float4 vb = *(const float4*)(B + (size_t)(bn + r) * K + kt + lcol);
            Bs[lcol + 0][r] = vb.x; Bs[lcol + 1][r] = vb.y;
            Bs[lcol + 2][r] = vb.z; Bs[lcol + 3][r] = vb.w;
        }
        __syncthreads();
#pragma unroll
        for (int k = 0; k < 16; ++k) {
            float a[8], b[8];
#pragma unroll
            for (int i = 0; i < 8; ++i) a[i] = As[k][(ty << 3) + i];
#pragma unroll
            for (int j = 0; j < 8; ++j) b[j] = Bs[k][(tx << 3) + j];
#pragma unroll
            for (int i = 0; i < 8; ++i)
#pragma unroll
                for (int j = 0; j < 8; ++j)
                    acc[i][j] = fmaf(a[i], b[j], acc[i][j]);
        }
        __syncthreads();
    }

    float* out3 = (DEST == 3) ? (out_is_fb ? (float*)g_OUT_FB : out_ext) : (float*)nullptr;

#pragma unroll
    for (int i = 0; i < 8; ++i) {
        int m = bm + (ty << 3) + i;
#pragma unroll
        for (int jg = 0; jg < 8; jg += 4) {
            int e = bn + (tx << 3) + jg;
            float4 v;
            v.x = acc[i][jg + 0] * scale;
            v.y = acc[i][jg + 1] * scale;
            v.z = acc[i][jg + 2] * scale;
            v.w = acc[i][jg + 3] * scale;
            if (DEST <= 2) {
                // m = n*BATCH + b ; e = h*DH + dh ; dest[(b,h,n,dh)]
                int n_ = m >> 1;     // BATCH == 2
                int bb = m & 1;
                int h  = e >> 6;     // DH == 64
                int dh = e & 63;
                float* dst = (DEST == 0) ? g_Q : (DEST == 1) ? g_K : g_V;
                *(float4*)(dst + (((size_t)(bb * NH + h) * SEQ + n_) * DH + dh)) = v;
            } else {
                v.x += bias[e + 0]; v.y += bias[e + 1];
                v.z += bias[e + 2]; v.w += bias[e + 3];
                *(float4*)(out3 + (size_t)m * EMB + e) = v;
            }
        }
    }
}

// ---------------------------------------------------------------------------
// Scores: S[bh, i, j] = sum_d Qs[bh,i,d] * K[bh,j,d]   (scale folded into Q)
// Tile 64x64, K=64 in chunks of 16. 256 threads, 4x4 per thread.
// ---------------------------------------------------------------------------
__global__ __launch_bounds__(256) void scores_kernel(float* __restrict__ attn_ext,
                                                     int attn_is_scratch)
{
    float* S = attn_is_scratch ? (float*)g_S : attn_ext;
    const int bh = blockIdx.z;
    const float* Qb = g_Q + (size_t)bh * SEQ * DH;
    const float* Kb = g_K + (size_t)bh * SEQ * DH;
    const int bi = blockIdx.y * 64;
    const int bj = blockIdx.x * 64;

    __shared__ float Qs[16][64];
    __shared__ float Ks[16][64];

    const int tid = threadIdx.x;
    const int tx = tid & 15;
    const int ty = tid >> 4;
    const int lrow = tid >> 2;        // 0..63
    const int lcol = (tid & 3) << 2;  // 0,4,8,12

    float acc[4][4];
#pragma unroll
    for (int i = 0; i < 4; ++i)
#pragma unroll
        for (int j = 0; j < 4; ++j) acc[i][j] = 0.0f;

#pragma unroll
    for (int kt = 0; kt < DH; kt += 16) {
        float4 va = *(const float4*)(Qb + (size_t)(bi + lrow) * DH + kt + lcol);
        Qs[lcol + 0][lrow] = va.x; Qs[lcol + 1][lrow] = va.y;
        Qs[lcol + 2][lrow] = va.z; Qs[lcol + 3][lrow] = va.w;
        float4 vb = *(const float4*)(Kb + (size_t)(bj + lrow) * DH + kt + lcol);
        Ks[lcol + 0][lrow] = vb.x; Ks[lcol + 1][lrow] = vb.y;
        Ks[lcol + 2][lrow] = vb.z; Ks[lcol + 3][lrow] = vb.w;
        __syncthreads();
#pragma unroll
        for (int k = 0; k < 16; ++k) {
            float a[4], b[4];
#pragma unroll
            for (int i = 0; i < 4; ++i) a[i] = Qs[k][(ty << 2) + i];
#pragma unroll
            for (int j = 0; j < 4; ++j) b[j] = Ks[k][(tx << 2) + j];
#pragma unroll
            for (int i = 0; i < 4; ++i)
#pragma unroll
                for (int j = 0; j < 4; ++j)
                    acc[i][j] = fmaf(a[i], b[j], acc[i][j]);
        }
        __syncthreads();
    }

#pragma unroll
    for (int i = 0; i < 4; ++i) {
        size_t row = (size_t)bh * SEQ + bi + (ty << 2) + i;
        float4 v = make_float4(acc[i][0], acc[i][1], acc[i][2], acc[i][3]);
        *(float4*)(S + row * SEQ + bj + (tx << 2)) = v;
    }
}

// ---------------------------------------------------------------------------
// Row softmax, in place. One block (256 threads) per row of 2048.
// ---------------------------------------------------------------------------
__global__ __launch_bounds__(256) void softmax_kernel(float* __restrict__ attn_ext,
                                                      int attn_is_scratch)
{
    float* S = attn_is_scratch ? (float*)g_S : attn_ext;
    float* p = S + (size_t)blockIdx.x * SEQ;
    const int tid = threadIdx.x;

    float4 v0 = ((float4*)p)[tid];
    float4 v1 = ((float4*)p)[tid + 256];

    float m = fmaxf(fmaxf(fmaxf(v0.x, v0.y), fmaxf(v0.z, v0.w)),
                    fmaxf(fmaxf(v1.x, v1.y), fmaxf(v1.z, v1.w)));

    __shared__ float redm[8];
    __shared__ float reds[8];

#pragma unroll
    for (int o = 16; o; o >>= 1) m = fmaxf(m, __shfl_xor_sync(0xffffffffu, m, o));
    if ((tid & 31) == 0) redm[tid >> 5] = m;
    __syncthreads();
    m = redm[0];
#pragma unroll
    for (int i = 1; i < 8; ++i) m = fmaxf(m, redm[i]);

    v0.x = __expf(v0.x - m); v0.y = __expf(v0.y - m);
    v0.z = __expf(v0.z - m); v0.w = __expf(v0.w - m);
    v1.x = __expf(v1.x - m); v1.y = __expf(v1.y - m);
    v1.z = __expf(v1.z - m); v1.w = __expf(v1.w - m);

    float s = v0.x + v0.y + v0.z + v0.w + v1.x + v1.y + v1.z + v1.w;
#pragma unroll
    for (int o = 16; o; o >>= 1) s += __shfl_xor_sync(0xffffffffu, s, o);
    if ((tid & 31) == 0) reds[tid >> 5] = s;
    __syncthreads();
    s = reds[0];
#pragma unroll
    for (int i = 1; i < 8; ++i) s += reds[i];

    float inv = 1.0f / s;
    v0.x *= inv; v0.y *= inv; v0.z *= inv; v0.w *= inv;
    v1.x *= inv; v1.y *= inv; v1.z *= inv; v1.w *= inv;

    ((float4*)p)[tid]       = v0;
    ((float4*)p)[tid + 256] = v1;
}

// ---------------------------------------------------------------------------
// O = attn @ V per (b,h).  M=2048 (tile 64), N=64 (full), K=2048 (chunks 32).
// Writes g_O in (n, b, e=h*64+dh) layout.
// ---------------------------------------------------------------------------
__global__ __launch_bounds__(256) void pv_kernel(const float* __restrict__ attn_ext,
                                                 int attn_is_scratch)
{
    const float* S = attn_is_scratch ? (const float*)g_S : attn_ext;
    const int bh = blockIdx.y;
    const int bi = blockIdx.x * 64;
    const float* Pb = S + (size_t)bh * SEQ * SEQ;
    const float* Vb = g_V + (size_t)bh * SEQ * DH;

    __shared__ float Ps[32][64];
    __shared__ float Vs[32][64];

    const int tid = threadIdx.x;
    const int tx = tid & 15;
    const int ty = tid >> 4;
    const int prow = tid >> 3;        // 0..31
    const int pcol = (tid & 7) << 2;  // 0..28
    const int vrow = tid >> 4;        // 0..15
    const int vcol = (tid & 15) << 2; // 0..60

    float acc[4][4];
#pragma unroll
    for (int i = 0; i < 4; ++i)
#pragma unroll
        for (int j = 0; j < 4; ++j) acc[i][j] = 0.0f;

    for (int kt = 0; kt < SEQ; kt += 32) {
#pragma unroll
        for (int p = 0; p < 2; ++p) {
            int r = (p << 5) + prow;
            float4 va = *(const float4*)(Pb + (size_t)(bi + r) * SEQ + kt + pcol);
            Ps[pcol + 0][r] = va.x; Ps[pcol + 1][r] = va.y;
            Ps[pcol + 2][r] = va.z; Ps[pcol + 3][r] = va.w;
            int kr = (p << 4) + vrow;
            float4 vv = *(const float4*)(Vb + (size_t)(kt + kr) * DH + vcol);
            *(float4*)&Vs[kr][vcol] = vv;
        }
        __syncthreads();
#pragma unroll
        for (int k = 0; k < 32; ++k) {
            float a[4], b[4];
#pragma unroll
            for (int i = 0; i < 4; ++i) a[i] = Ps[k][(ty << 2) + i];
#pragma unroll
            for (int j = 0; j < 4; ++j) b[j] = Vs[k][(tx << 2) + j];
#pragma unroll
            for (int i = 0; i < 4; ++i)
#pragma unroll
                for (int j = 0; j < 4; ++j)
                    acc[i][j] = fmaf(a[i], b[j], acc[i][j]);
        }
        __syncthreads();
    }

    const int b_ = bh >> 4;   // NH == 16
    const int h  = bh & 15;
#pragma unroll
    for (int i = 0; i < 4; ++i) {
        int n_ = bi + (ty << 2) + i;
        int e  = h * DH + (tx << 2);
        float4 v = make_float4(acc[i][0], acc[i][1], acc[i][2], acc[i][3]);
        *(float4*)(g_O + ((size_t)n_ * BATCH + b_) * EMB + e) = v;
    }
}

// ---------------------------------------------------------------------------
// Launch
// ---------------------------------------------------------------------------
extern "C" void kernel_launch(void* const* d_in, const int* in_sizes, int n_in,
                              void* d_out, int out_size)
{
    const float* query = (const float*)d_in[0];
    const float* key   = (const float*)d_in[1];
    const float* value = (const float*)d_in[2];
    const float* Wq    = (const float*)d_in[3];
    const float* Wk    = (const float*)d_in[4];
    const float* Wv    = (const float*)d_in[5];
    const float* Wo    = (const float*)d_in[6];
    const float* bo    = (const float*)d_in[7];

    // Output layout: flattened tuple (out, attn). Handle the degenerate cases
    // where the harness only checks one of them.
    float* outp = (float*)d_out;
    float* attnp = nullptr;
    int attn_is_scratch = 0;
    int out_is_fb = 0;
    size_t osz = (size_t)out_size;
    if (osz >= OUT_ELEMS + ATTN_ELEMS) {
        attnp = (float*)d_out + OUT_ELEMS;
    } else if (osz == ATTN_ELEMS) {
        attnp = (float*)d_out;
        out_is_fb = 1;
    } else {
        attn_is_scratch = 1;
    }

    const float scale = 0.125f;  // DH^-0.5 = 64^-0.5

    dim3 gProj(EMB / 128, MROWS / 128);  // (8, 32)
    sgemm128<0><<<gProj, 256>>>(query, Wq, nullptr, scale, nullptr, 0);
    sgemm128<1><<<gProj, 256>>>(key,   Wk, nullptr, 1.0f,  nullptr, 0);
    sgemm128<2><<<gProj, 256>>>(value, Wv, nullptr, 1.0f,  nullptr, 0);

    dim3 gS(SEQ / 64, SEQ / 64, BATCH * NH);  // (32, 32, 32)
    scores_kernel<<<gS, 256>>>(attnp, attn_is_scratch);

    softmax_kernel<<<BATCH * NH * SEQ, 256>>>(attnp, attn_is_scratch);

    dim3 gPV(SEQ / 64, BATCH * NH);  // (32, 32)
    pv_kernel<<<gPV, 256>>>(attnp, attn_is_scratch);

    sgemm128<3><<<gProj, 256>>>(nullptr, Wo, bo, 1.0f, outp, out_is_fb);
}

// round 2
// speedup vs baseline: 1.6676x; 1.6676x over previous
#include <cuda_runtime.h>
#include <cstdint>

#define SEQ   2048
#define BATCH 2
#define EMB   1024
#define NH    16
#define DH    64
#define MROWS (SEQ * BATCH)  // 4096

static const size_t OUT_ELEMS  = (size_t)MROWS * EMB;            // 4,194,304
static const size_t ATTN_ELEMS = (size_t)BATCH * NH * SEQ * SEQ; // 134,217,728

// Scratch (allocation-free rule: __device__ globals)
__device__ float g_Q[BATCH * NH * SEQ * DH];   // (b,h,n,dh), scale folded in
__device__ float g_K[BATCH * NH * SEQ * DH];
__device__ float g_V[BATCH * NH * SEQ * DH];
__device__ float g_O[MROWS * EMB];             // (n,b,e) layout
__device__ float g_S[BATCH * NH * SEQ * SEQ];  // attn fallback scratch
__device__ float g_OUT_FB[MROWS * EMB];        // out fallback scratch

__device__ __forceinline__ uint32_t f2tf(float x) {
    uint32_t r;
    asm("cvt.rna.tf32.f32 %0, %1;" : "=r"(r) : "f"(x));
    return r;
}

__device__ __forceinline__ void mma8(float* c, const uint32_t* a, const uint32_t* b) {
    asm volatile(
        "mma.sync.aligned.m16n8k8.row.col.f32.tf32.tf32.f32 "
        "{%0,%1,%2,%3}, {%4,%5,%6,%7}, {%8,%9}, {%0,%1,%2,%3};\n"
        : "+f"(c[0]), "+f"(c[1]), "+f"(c[2]), "+f"(c[3])
        : "r"(a[0]), "r"(a[1]), "r"(a[2]), "r"(a[3]), "r"(b[0]), "r"(b[1]));
}

// ---------------------------------------------------------------------------
// TF32 GEMM, C[M,N] = A[M,K] * B[N,K]^T, M=4096, N=K=1024.
// Block tile 128x128, K staged 16. 8 warps: warp grid 2(m) x 4(n), warp 64x32.
// DEST 0/1/2: scatter to g_Q/g_K/g_V (b,h,n,dh) with scale.
// DEST 3:     A = g_O, out = row-major + bias.
// ---------------------------------------------------------------------------
template <int DEST>
__global__ __launch_bounds__(256) void gemm_tf32(const float* __restrict__ A_ext,
                                                 const float* __restrict__ Bm,
                                                 const float* __restrict__ bias,
                                                 float scale,
                                                 float* __restrict__ out_ext,
                                                 int out_is_fb)
{
    __shared__ uint32_t As[2][16][132];
    __shared__ uint32_t Bs[2][16][132];

    const float* A = (DEST == 3) ? (const float*)g_O : A_ext;
    const int K = EMB;
    const int bm = blockIdx.y * 128;
    const int bn = blockIdx.x * 128;
    const int tid = threadIdx.x;
    const int lrow = tid >> 1;
    const int lk = (tid & 1) * 8;
    const int w = tid >> 5;
    const int lane = tid & 31;
    const int wm = (w & 1) * 64;
    const int wn = (w >> 1) * 32;
    const int grp = lane >> 2;
    const int tig = lane & 3;

    float c[4][4][4];
#pragma unroll
    for (int mt = 0; mt < 4; ++mt)
#pragma unroll
        for (int nt = 0; nt < 4; ++nt)
#pragma unroll
            for (int i = 0; i < 4; ++i) c[mt][nt][i] = 0.0f;

    const float* pa = A + (size_t)(bm + lrow) * K + lk;
    const float* pb = Bm + (size_t)(bn + lrow) * K + lk;

    float4 ra0 = *(const float4*)pa;
    float4 ra1 = *(const float4*)(pa + 4);
    float4 rb0 = *(const float4*)pb;
    float4 rb1 = *(const float4*)(pb + 4);

    As[0][lk + 0][lrow] = f2tf(ra0.x); As[0][lk + 1][lrow] = f2tf(ra0.y);
    As[0][lk + 2][lrow] = f2tf(ra0.z); As[0][lk + 3][lrow] = f2tf(ra0.w);
    As[0][lk + 4][lrow] = f2tf(ra1.x); As[0][lk + 5][lrow] = f2tf(ra1.y);
    As[0][lk + 6][lrow] = f2tf(ra1.z); As[0][lk + 7][lrow] = f2tf(ra1.w);
    Bs[0][lk + 0][lrow] = f2tf(rb0.x); Bs[0][lk + 1][lrow] = f2tf(rb0.y);
    Bs[0][lk + 2][lrow] = f2tf(rb0.z); Bs[0][lk + 3][lrow] = f2tf(rb0.w);
    Bs[0][lk + 4][lrow] = f2tf(rb1.x); Bs[0][lk + 5][lrow] = f2tf(rb1.y);
    Bs[0][lk + 6][lrow] = f2tf(rb1.z); Bs[0][lk + 7][lrow] = f2tf(rb1.w);
    __syncthreads();

    const int nk = K / 16;
    for (int kt = 0; kt < nk; ++kt) {
        const int buf = kt & 1;
        if (kt + 1 < nk) {
            const float* qa = pa + (kt + 1) * 16;
            ra0 = *(const float4*)qa; ra1 = *(const float4*)(qa + 4);
            const float* qb = pb + (kt + 1) * 16;
            rb0 = *(const float4*)qb; rb1 = *(const float4*)(qb + 4);
        }
#pragma unroll
        for (int ks = 0; ks < 16; ks += 8) {
            uint32_t af[4][4], bf[4][2];
#pragma unroll
            for (int mt = 0; mt < 4; ++mt) {
                int m0 = wm + mt * 16 + grp;
                af[mt][0] = As[buf][ks + tig][m0];
                af[mt][1] = As[buf][ks + tig][m0 + 8];
                af[mt][2] = As[buf][ks + tig + 4][m0];
                af[mt][3] = As[buf][ks + tig + 4][m0 + 8];
            }
#pragma unroll
            for (int nt = 0; nt < 4; ++nt) {
                int n0 = wn + nt * 8 + grp;
                bf[nt][0] = Bs[buf][ks + tig][n0];
                bf[nt][1] = Bs[buf][ks + tig + 4][n0];
            }
#pragma unroll
            for (int mt = 0; mt < 4; ++mt)
#pragma unroll
                for (int nt = 0; nt < 4; ++nt)
                    mma8(c[mt][nt], af[mt], bf[nt]);
        }
        if (kt + 1 < nk) {
            const int nb = buf ^ 1;
            As[nb][lk + 0][lrow] = f2tf(ra0.x); As[nb][lk + 1][lrow] = f2tf(ra0.y);
            As[nb][lk + 2][lrow] = f2tf(ra0.z); As[nb][lk + 3][lrow] = f2tf(ra0.w);
            As[nb][lk + 4][lrow] = f2tf(ra1.x); As[nb][lk + 5][lrow] = f2tf(ra1.y);
            As[nb][lk + 6][lrow] = f2tf(ra1.z); As[nb][lk + 7][lrow] = f2tf(ra1.w);
            Bs[nb][lk + 0][lrow] = f2tf(rb0.x); Bs[nb][lk + 1][lrow] = f2tf(rb0.y);
            Bs[nb][lk + 2][lrow] = f2tf(rb0.z); Bs[nb][lk + 3][lrow] = f2tf(rb0.w);
            Bs[nb][lk + 4][lrow] = f2tf(rb1.x); Bs[nb][lk + 5][lrow] = f2tf(rb1.y);
            Bs[nb][lk + 6][lrow] = f2tf(rb1.z); Bs[nb][lk + 7][lrow] = f2tf(rb1.w);
        }
        __syncthreads();
    }

    float* out3 = (DEST == 3) ? (out_is_fb ? (float*)g_OUT_FB : out_ext) : (float*)nullptr;
    float* dst = (DEST == 0) ? g_Q : (DEST == 1) ? g_K : (DEST == 2) ? g_V : (float*)nullptr;

#pragma unroll
    for (int mt = 0; mt < 4; ++mt) {
#pragma unroll
        for (int nt = 0; nt < 4; ++nt) {
            const int e = bn + wn + nt * 8 + 2 * tig;
#pragma unroll
            for (int h2 = 0; h2 < 2; ++h2) {
                const int m = bm + wm + mt * 16 + grp + h2 * 8;
                float2 v = make_float2(c[mt][nt][h2 * 2 + 0] * scale,
                                       c[mt][nt][h2 * 2 + 1] * scale);
                if (DEST <= 2) {
                    int n_ = m >> 1;  // BATCH == 2
                    int bb = m & 1;
                    int hh = e >> 6;  // DH == 64
                    int dh = e & 63;
                    *(float2*)(dst + (((size_t)(bb * NH + hh) * SEQ + n_) * DH + dh)) = v;
                } else {
                    v.x += bias[e];
                    v.y += bias[e + 1];
                    *(float2*)(out3 + (size_t)m * EMB + e) = v;
                }
            }
        }
    }
}

// ---------------------------------------------------------------------------
// Scores (TF32): S[bh,i,j] = sum_d Q[bh,i,d] * K[bh,j,d] (scale folded in Q).
// Block tile 128x128, K=64 staged 16.
// ---------------------------------------------------------------------------
__global__ __launch_bounds__(256) void scores_tf32(float* __restrict__ attn_ext,
                                                   int attn_is_scratch)
{
    __shared__ uint32_t As[2][16][132];
    __shared__ uint32_t Bs[2][16][132];

    float* S = attn_is_scratch ? (float*)g_S : attn_ext;
    const int bh = blockIdx.z;
    const float* Qb = g_Q + (size_t)bh * SEQ * DH;
    const float* Kb = g_K + (size_t)bh * SEQ * DH;
    const int bm = blockIdx.y * 128;
    const int bn = blockIdx.x * 128;
    const int tid = threadIdx.x;
    const int lrow = tid >> 1;
    const int lk = (tid & 1) * 8;
    const int w = tid >> 5;
    const int lane = tid & 31;
    const int wm = (w & 1) * 64;
    const int wn = (w >> 1) * 32;
    const int grp = lane >> 2;
    const int tig = lane & 3;

    float c[4][4][4];
#pragma unroll
    for (int mt = 0; mt < 4; ++mt)
#pragma unroll
        for (int nt = 0; nt < 4; ++nt)
#pragma unroll
            for (int i = 0; i < 4; ++i) c[mt][nt][i] = 0.0f;

    const float* pa = Qb + (size_t)(bm + lrow) * DH + lk;
    const float* pb = Kb + (size_t)(bn + lrow) * DH + lk;

    float4 ra0 = *(const float4*)pa;
    float4 ra1 = *(const float4*)(pa + 4);
    float4 rb0 = *(const float4*)pb;
    float4 rb1 = *(const float4*)(pb + 4);

    As[0][lk + 0][lrow] = f2tf(ra0.x); As[0][lk + 1][lrow] = f2tf(ra0.y);
    As[0][lk + 2][lrow] = f2tf(ra0.z); As[0][lk + 3][lrow] = f2tf(ra0.w);
    As[0][lk + 4][lrow] = f2tf(ra1.x); As[0][lk + 5][lrow] = f2tf(ra1.y);
    As[0][lk + 6][lrow] = f2tf(ra1.z); As[0][lk + 7][lrow] = f2tf(ra1.w);
    Bs[0][lk + 0][lrow] = f2tf(rb0.x); Bs[0][lk + 1][lrow] = f2tf(rb0.y);
    Bs[0][lk + 2][lrow] = f2tf(rb0.z); Bs[0][lk + 3][lrow] = f2tf(rb0.w);
    Bs[0][lk + 4][lrow] = f2tf(rb1.x); Bs[0][lk + 5][lrow] = f2tf(rb1.y);
    Bs[0][lk + 6][lrow] = f2tf(rb1.z); Bs[0][lk + 7][lrow] = f2tf(rb1.w);
    __syncthreads();

    const int nk = DH / 16;  // 4
#pragma unroll
    for (int kt = 0; kt < nk; ++kt) {
        const int buf = kt & 1;
        if (kt + 1 < nk) {
            const float* qa = pa + (kt + 1) * 16;
            ra0 = *(const float4*)qa; ra1 = *(const float4*)(qa + 4);
            const float* qb = pb + (kt + 1) * 16;
            rb0 = *(const float4*)qb; rb1 = *(const float4*)(qb + 4);
        }
#pragma unroll
        for (int ks = 0; ks < 16; ks += 8) {
            uint32_t af[4][4], bf[4][2];
#pragma unroll
            for (int mt = 0; mt < 4; ++mt) {
                int m0 = wm + mt * 16 + grp;
                af[mt][0] = As[buf][ks + tig][m0];
                af[mt][1] = As[buf][ks + tig][m0 + 8];
                af[mt][2] = As[buf][ks + tig + 4][m0];
                af[mt][3] = As[buf][ks + tig + 4][m0 + 8];
            }
#pragma unroll
            for (int nt = 0; nt < 4; ++nt) {
                int n0 = wn + nt * 8 + grp;
                bf[nt][0] = Bs[buf][ks + tig][n0];
                bf[nt][1] = Bs[buf][ks + tig + 4][n0];
            }
#pragma unroll
            for (int mt = 0; mt < 4; ++mt)
#pragma unroll
                for (int nt = 0; nt < 4; ++nt)
                    mma8(c[mt][nt], af[mt], bf[nt]);
        }
        if (kt + 1 < nk) {
            const int nb = buf ^ 1;
            As[nb][lk + 0][lrow] = f2tf(ra0.x); As[nb][lk + 1][lrow] = f2tf(ra0.y);
            As[nb][lk + 2][lrow] = f2tf(ra0.z); As[nb][lk + 3][lrow] = f2tf(ra0.w);
            As[nb][lk + 4][lrow] = f2tf(ra1.x); As[nb][lk + 5][lrow] = f2tf(ra1.y);
            As[nb][lk + 6][lrow] = f2tf(ra1.z); As[nb][lk + 7][lrow] = f2tf(ra1.w);
            Bs[nb][lk + 0][lrow] = f2tf(rb0.x); Bs[nb][lk + 1][lrow] = f2tf(rb0.y);
            Bs[nb][lk + 2][lrow] = f2tf(rb0.z); Bs[nb][lk + 3][lrow] = f2tf(rb0.w);
            Bs[nb][lk + 4][lrow] = f2tf(rb1.x); Bs[nb][lk + 5][lrow] = f2tf(rb1.y);
            Bs[nb][lk + 6][lrow] = f2tf(rb1.z); Bs[nb][lk + 7][lrow] = f2tf(rb1.w);
        }
        __syncthreads();
    }

#pragma unroll
    for (int mt = 0; mt < 4; ++mt) {
#pragma unroll
        for (int nt = 0; nt < 4; ++nt) {
            const int col = bn + wn + nt * 8 + 2 * tig;
#pragma unroll
            for (int h2 = 0; h2 < 2; ++h2) {
                const int m = bm + wm + mt * 16 + grp + h2 * 8;
                float2 v = make_float2(c[mt][nt][h2 * 2 + 0], c[mt][nt][h2 * 2 + 1]);
                *(float2*)(S + ((size_t)bh * SEQ + m) * SEQ + col) = v;
            }
        }
    }
}

// ---------------------------------------------------------------------------
// Row softmax, in place. One block (256 threads) per row of 2048.
// ---------------------------------------------------------------------------
__global__ __launch_bounds__(256) void softmax_kernel(float* __restrict__ attn_ext,
                                                      int attn_is_scratch)
{
    float* S = attn_is_scratch ? (float*)g_S : attn_ext;
    float* p = S + (size_t)blockIdx.x * SEQ;
    const int tid = threadIdx.x;

    float4 v0 = ((float4*)p)[tid];
    float4 v1 = ((float4*)p)[tid + 256];

    float m = fmaxf(fmaxf(fmaxf(v0.x, v0.y), fmaxf(v0.z, v0.w)),
                    fmaxf(fmaxf(v1.x, v1.y), fmaxf(v1.z, v1.w)));

    __shared__ float redm[8];
    __shared__ float reds[8];

#pragma unroll
    for (int o = 16; o; o >>= 1) m = fmaxf(m, __shfl_xor_sync(0xffffffffu, m, o));
    if ((tid & 31) == 0) redm[tid >> 5] = m;
    __syncthreads();
    m = redm[0];
#pragma unroll
    for (int i = 1; i < 8; ++i) m = fmaxf(m, redm[i]);

    v0.x = __expf(v0.x - m); v0.y = __expf(v0.y - m);
    v0.z = __expf(v0.z - m); v0.w = __expf(v0.w - m);
    v1.x = __expf(v1.x - m); v1.y = __expf(v1.y - m);
    v1.z = __expf(v1.z - m); v1.w = __expf(v1.w - m);

    float s = v0.x + v0.y + v0.z + v0.w + v1.x + v1.y + v1.z + v1.w;
#pragma unroll
    for (int o = 16; o; o >>= 1) s += __shfl_xor_sync(0xffffffffu, s, o);
    if ((tid & 31) == 0) reds[tid >> 5] = s;
    __syncthreads();
    s = reds[0];
#pragma unroll
    for (int i = 1; i < 8; ++i) s += reds[i];

    float inv = 1.0f / s;
    v0.x *= inv; v0.y *= inv; v0.z *= inv; v0.w *= inv;
    v1.x *= inv; v1.y *= inv; v1.z *= inv; v1.w *= inv;

    ((float4*)p)[tid]       = v0;
    ((float4*)p)[tid + 256] = v1;
}

// ---------------------------------------------------------------------------
// PV (TF32): O = attn @ V per (b,h). M=2048 (tile 128), N=64, K=2048 (stage 16).
// 8 warps: warp grid 4(m) x 2(n), warp tile 32x32.
// ---------------------------------------------------------------------------
__global__ __launch_bounds__(256) void pv_tf32(const float* __restrict__ attn_ext,
                                               int attn_is_scratch)
{
    __shared__ uint32_t As[2][16][132];  // P tile: [k][m]
    __shared__ uint32_t Bs[2][16][68];   // V tile: [k][n]

    const float* Sm = attn_is_scratch ? (const float*)g_S : attn_ext;
    const int bh = blockIdx.y;
    const float* Pb = Sm + (size_t)bh * SEQ * SEQ;
    const float* Vb = g_V + (size_t)bh * SEQ * DH;
    const int bm = blockIdx.x * 128;

    const int tid = threadIdx.x;
    const int lrow = tid >> 1;
    const int lk = (tid & 1) * 8;
    const int vrow = tid >> 4;        // 0..15
    const int vcol = (tid & 15) * 4;  // 0..60
    const int w = tid >> 5;
    const int lane = tid & 31;
    const int wm = (w & 3) * 32;
    const int wn = (w >> 2) * 32;
    const int grp = lane >> 2;
    const int tig = lane & 3;

    float c[2][4][4];
#pragma unroll
    for (int mt = 0; mt < 2; ++mt)
#pragma unroll
        for (int nt = 0; nt < 4; ++nt)
#pragma unroll
            for (int i = 0; i < 4; ++i) c[mt][nt][i] = 0.0f;

    const float* pa = Pb + (size_t)(bm + lrow) * SEQ + lk;

    float4 ra0 = *(const float4*)pa;
    float4 ra1 = *(const float4*)(pa + 4);
    float4 rv  = *(const float4*)(Vb + (size_t)vrow * DH + vcol);

    As[0][lk + 0][lrow] = f2tf(ra0.x); As[0][lk + 1][lrow] = f2tf(ra0.y);
    As[0][lk + 2][lrow] = f2tf(ra0.z); As[0][lk + 3][lrow] = f2tf(ra0.w);
    As[0][lk + 4][lrow] = f2tf(ra1.x); As[0][lk + 5][lrow] = f2tf(ra1.y);
    As[0][lk + 6][lrow] = f2tf(ra1.z); As[0][lk + 7][lrow] = f2tf(ra1.w);
    Bs[0][vrow][vcol + 0] = f2tf(rv.x); Bs[0][vrow][vcol + 1] = f2tf(rv.y);
    Bs[0][vrow][vcol + 2] = f2tf(rv.z); Bs[0][vrow][vcol + 3] = f2tf(rv.w);
    __syncthreads();

    const int nk = SEQ / 16;  // 128
    for (int kt = 0; kt < nk; ++kt) {
        const int buf = kt & 1;
        if (kt + 1 < nk) {
            const float* qa = pa + (kt + 1) * 16;
            ra0 = *(const float4*)qa; ra1 = *(const float4*)(qa + 4);
            rv = *(const float4*)(Vb + (size_t)((kt + 1) * 16 + vrow) * DH + vcol);
        }
#pragma unroll
        for (int ks = 0; ks < 16; ks += 8) {
            uint32_t af[2][4], bf[4][2];
#pragma unroll
            for (int mt = 0; mt < 2; ++mt) {
                int m0 = wm + mt * 16 + grp;
                af[mt][0] = As[buf][ks + tig][m0];
                af[mt][1] = As[buf][ks + tig][m0 + 8];
                af[mt][2] = As[buf][ks + tig + 4][m0];
                af[mt][3] = As[buf][ks + tig + 4][m0 + 8];
            }
#pragma unroll
            for (int nt = 0; nt < 4; ++nt) {
                int n0 = wn + nt * 8 + grp;
                bf[nt][0] = Bs[buf][ks + tig][n0];
                bf[nt][1] = Bs[buf][ks + tig + 4][n0];
            }
#pragma unroll
            for (int mt = 0; mt < 2; ++mt)
#pragma unroll
                for (int nt = 0; nt < 4; ++nt)
                    mma8(c[mt][nt], af[mt], bf[nt]);
        }
        if (kt + 1 < nk) {
            const int nb = buf ^ 1;
            As[nb][lk + 0][lrow] = f2tf(ra0.x); As[nb][lk + 1][lrow] = f2tf(ra0.y);
            As[nb][lk + 2][lrow] = f2tf(ra0.z); As[nb][lk + 3][lrow] = f2tf(ra0.w);
            As[nb][lk + 4][lrow] = f2tf(ra1.x); As[nb][lk + 5][lrow] = f2tf(ra1.y);
            As[nb][lk + 6][lrow] = f2tf(ra1.z); As[nb][lk + 7][lrow] = f2tf(ra1.w);
            Bs[nb][vrow][vcol + 0] = f2tf(rv.x); Bs[nb][vrow][vcol + 1] = f2tf(rv.y);
            Bs[nb][vrow][vcol + 2] = f2tf(rv.z); Bs[nb][vrow][vcol + 3] = f2tf(rv.w);
        }
        __syncthreads();
    }

    const int b_ = bh >> 4;  // NH == 16
    const int h = bh & 15;
#pragma unroll
    for (int mt = 0; mt < 2; ++mt) {
#pragma unroll
        for (int nt = 0; nt < 4; ++nt) {
            const int dh = wn + nt * 8 + 2 * tig;
            const int e = h * DH + dh;
#pragma unroll
            for (int h2 = 0; h2 < 2; ++h2) {
                const int i = bm + wm + mt * 16 + grp + h2 * 8;
                float2 v = make_float2(c[mt][nt][h2 * 2 + 0], c[mt][nt][h2 * 2 + 1]);
                *(float2*)(g_O + ((size_t)i * BATCH + b_) * EMB + e) = v;
            }
        }
    }
}

// ---------------------------------------------------------------------------
// Launch
// ---------------------------------------------------------------------------
extern "C" void kernel_launch(void* const* d_in, const int* in_sizes, int n_in,
                              void* d_out, int out_size)
{
    const float* query = (const float*)d_in[0];
    const float* key   = (const float*)d_in[1];
    const float* value = (const float*)d_in[2];
    const float* Wq    = (const float*)d_in[3];
    const float* Wk    = (const float*)d_in[4];
    const float* Wv    = (const float*)d_in[5];
    const float* Wo    = (const float*)d_in[6];
    const float* bo    = (const float*)d_in[7];

    float* outp = (float*)d_out;
    float* attnp = nullptr;
    int attn_is_scratch = 0;
    int out_is_fb = 0;
    size_t osz = (size_t)out_size;
    if (osz >= OUT_ELEMS + ATTN_ELEMS) {
        attnp = (float*)d_out + OUT_ELEMS;
    } else if (osz == ATTN_ELEMS) {
        attnp = (float*)d_out;
        out_is_fb = 1;
    } else {
        attn_is_scratch = 1;
    }

    const float scale = 0.125f;  // DH^-0.5

    dim3 gProj(EMB / 128, MROWS / 128);  // (8, 32)
    gemm_tf32<0><<<gProj, 256>>>(query, Wq, nullptr, scale, nullptr, 0);
    gemm_tf32<1><<<gProj, 256>>>(key,   Wk, nullptr, 1.0f,  nullptr, 0);
    gemm_tf32<2><<<gProj, 256>>>(value, Wv, nullptr, 1.0f,  nullptr, 0);

    dim3 gS(SEQ / 128, SEQ / 128, BATCH * NH);  // (16, 16, 32)
    scores_tf32<<<gS, 256>>>(attnp, attn_is_scratch);

    softmax_kernel<<<BATCH * NH * SEQ, 256>>>(attnp, attn_is_scratch);

    dim3 gPV(SEQ / 128, BATCH * NH);  // (16, 32)
    pv_tf32<<<gPV, 256>>>(attnp, attn_is_scratch);

    gemm_tf32<3><<<gProj, 256>>>(nullptr, Wo, bo, 1.0f, outp, out_is_fb);
}